// round 6
// baseline (speedup 1.0000x reference)
#include <cuda_runtime.h>

// Problem constants (fixed by the dataset)
static constexpr int NN  = 50000;   // nodes
static constexpr int NE  = 400000;  // edges
static constexpr int F0  = 128;     // input features
static constexpr int F1  = 256;     // hidden 1
static constexpr int F2  = 784;     // hidden 2
static constexpr int NC  = 10;      // classes

// ---------------- device scratch (static, allocation-free) ----------------
// Referenced ONLY from device code (host-side use => cudaErrorInvalidAddressSpace).
__device__ int   g_e64;                            // 1 if edge_index is int64
__device__ int   g_src32[NE];                      // clean int32 src indices
__device__ int   g_dst32[NE];                      // clean int32 dst indices
__device__ float g_dinv[NN];                       // deg accumulator -> deg^-1/2
__device__ float g_norm[NE];                       // edge norm
__device__ float g_h1  [(size_t)NN * F1];          // x @ W1
__device__ float g_agg1[(size_t)NN * F1];          // layer-1 pre-relu output
__device__ float g_h2  [(size_t)NN * F2];          // relu(agg1) @ W2
__device__ float g_agg2[(size_t)NN * F2];          // layer-2 pre-relu output

// ---------------- dtype detection + index materialization ----------------
// If edge_index is int64 with values < 2^31, every odd 32-bit word is 0.
// With real int32 data those words are random node ids; P[64 zeros] ~ 0.
__global__ void k_detect(const unsigned int* __restrict__ ei32) {
    if (threadIdx.x == 0 && blockIdx.x == 0) {
        int all0 = 1;
        #pragma unroll 1
        for (int i = 0; i < 64; i++)
            if (ei32[2 * i + 1] != 0u) { all0 = 0; break; }
        g_e64 = all0;
    }
}

__device__ __forceinline__ int edge_idx(const void* ei, int half, int e) {
    if (g_e64) return (int)((const long long*)ei)[(size_t)half * NE + e];
    return ((const int*)ei)[(size_t)half * NE + e];
}

// Convert indices to clean int32 arrays (one-time, small).
__global__ void k_convert_idx(const void* __restrict__ ei) {
    int e = blockIdx.x * blockDim.x + threadIdx.x;
    if (e < NE) {
        g_src32[e] = edge_idx(ei, 0, e);
        g_dst32[e] = edge_idx(ei, 1, e);
    }
}

// ---------------- degree / norm kernels ----------------
__global__ void k_deg_init() {
    int i = blockIdx.x * blockDim.x + threadIdx.x;
    if (i < NN) g_dinv[i] = 1.0f;   // reuse g_dinv as deg accumulator first
}

__global__ void k_deg_acc() {
    int e = blockIdx.x * blockDim.x + threadIdx.x;
    if (e < NE) atomicAdd(&g_dinv[g_dst32[e]], 1.0f);
}

__global__ void k_dinv() {
    int i = blockIdx.x * blockDim.x + threadIdx.x;
    if (i < NN) g_dinv[i] = rsqrtf(g_dinv[i]);
}

__global__ void k_norm() {
    int e = blockIdx.x * blockDim.x + threadIdx.x;
    if (e < NE) g_norm[e] = g_dinv[g_src32[e]] * g_dinv[g_dst32[e]];
}

// ---------------- tiled fp32 GEMM ----------------
// LAYER==1: g_h1 = A(x) @ W1;            M=NN, N=F1, K=F0
// LAYER==2: g_h2 = relu(g_agg1) @ W2;    M=NN, N=F2, K=F1
// BM=BN=64, BK=16, 256 threads, 4x4 micro-tile per thread.
template <int LAYER>
__global__ void gemm64(const float* __restrict__ Aparam,
                       const float* __restrict__ B,
                       int M, int N, int K) {
    const float* __restrict__ A = (LAYER == 1) ? Aparam : g_agg1;
    float* __restrict__ C = (LAYER == 1) ? g_h1 : g_h2;

    constexpr int BM = 64, BN = 64, BK = 16;
    __shared__ __align__(16) float As[BK][BM + 4];
    __shared__ __align__(16) float Bs[BK][BN];

    const int tid = threadIdx.x;
    const int bm = blockIdx.x * BM;
    const int bn = blockIdx.y * BN;
    const int tx = tid & 15;        // 0..15 -> N micro
    const int ty = tid >> 4;        // 0..15 -> M micro

    const int arow = tid >> 2;      // 0..63 : A row within tile
    const int ak   = (tid & 3) * 4; // k offset (float4 along K)
    const int brow = tid >> 4;      // 0..15 : B k-row within tile
    const int bcol = (tid & 15) * 4;// col offset (float4 along N)

    float acc[4][4] = {};

    for (int k0 = 0; k0 < K; k0 += BK) {
        // --- load A tile (transposed into As[k][m]) ---
        float4 a = make_float4(0.f, 0.f, 0.f, 0.f);
        if (bm + arow < M)
            a = *(const float4*)(A + (size_t)(bm + arow) * K + k0 + ak);
        if (LAYER == 2) {   // fuse relu of layer-1 output
            a.x = fmaxf(a.x, 0.f); a.y = fmaxf(a.y, 0.f);
            a.z = fmaxf(a.z, 0.f); a.w = fmaxf(a.w, 0.f);
        }
        As[ak + 0][arow] = a.x;
        As[ak + 1][arow] = a.y;
        As[ak + 2][arow] = a.z;
        As[ak + 3][arow] = a.w;

        // --- load B tile ---
        float4 b = make_float4(0.f, 0.f, 0.f, 0.f);
        if (bn + bcol < N)   // N % 4 == 0 so float4 is all-or-nothing
            b = *(const float4*)(B + (size_t)(k0 + brow) * N + bn + bcol);
        *(float4*)&Bs[brow][bcol] = b;

        __syncthreads();

        #pragma unroll
        for (int kk = 0; kk < BK; kk++) {
            float ar[4], br[4];
            *(float4*)ar = *(const float4*)&As[kk][ty * 4];
            *(float4*)br = *(const float4*)&Bs[kk][tx * 4];
            #pragma unroll
            for (int i = 0; i < 4; i++)
                #pragma unroll
                for (int j = 0; j < 4; j++)
                    acc[i][j] += ar[i] * br[j];
        }
        __syncthreads();
    }

    const int col = bn + tx * 4;
    if (col < N) {
        #pragma unroll
        for (int i = 0; i < 4; i++) {
            int row = bm + ty * 4 + i;
            if (row < M)
                *(float4*)(C + (size_t)row * N + col) =
                    make_float4(acc[i][0], acc[i][1], acc[i][2], acc[i][3]);
        }
    }
}

// ---------------- aggregation init: agg = h * self_norm + bias ----------------
template <int LAYER>
__global__ void k_agg_init(const float* __restrict__ bias, int F4, int total4) {
    const float* __restrict__ h = (LAYER == 1) ? g_h1 : g_h2;
    float* __restrict__ agg = (LAYER == 1) ? g_agg1 : g_agg2;

    int idx = blockIdx.x * blockDim.x + threadIdx.x;
    if (idx >= total4) return;
    int node = idx / F4;
    int q = idx - node * F4;
    float sn = g_dinv[node];
    sn *= sn;                       // self_norm = 1/deg
    float4 v = *(const float4*)(h + (size_t)idx * 4);
    float4 b = ((const float4*)bias)[q];
    v.x = v.x * sn + b.x; v.y = v.y * sn + b.y;
    v.z = v.z * sn + b.z; v.w = v.w * sn + b.w;
    *(float4*)(agg + (size_t)idx * 4) = v;
}

// ---------------- edge scatter: agg[dst] += h[src] * norm ----------------
template <int LAYER>
__global__ void k_scatter(int F4, long long total) {
    const float* __restrict__ h = (LAYER == 1) ? g_h1 : g_h2;
    float* __restrict__ agg = (LAYER == 1) ? g_agg1 : g_agg2;

    long long idx = (long long)blockIdx.x * blockDim.x + threadIdx.x;
    if (idx >= total) return;
    int e = (int)(idx / F4);
    int q = (int)(idx - (long long)e * F4);
    int s = g_src32[e];
    int d = g_dst32[e];
    float w = g_norm[e];
    float4 v = *(const float4*)(h + (size_t)s * (F4 * 4) + q * 4);
    float* o = agg + (size_t)d * (F4 * 4) + q * 4;
    atomicAdd(o + 0, v.x * w);
    atomicAdd(o + 1, v.y * w);
    atomicAdd(o + 2, v.z * w);
    atomicAdd(o + 3, v.w * w);
}

// ---------------- classifier + log_softmax (warp per node) ----------------
__global__ void k_classify(const float* __restrict__ Wc, const float* __restrict__ bc,
                           float* __restrict__ out) {
    __shared__ float sW[F2 * NC];  // 31360 B
    for (int i = threadIdx.x; i < F2 * NC; i += blockDim.x)
        sW[i] = Wc[i];
    __syncthreads();

    const int warp = threadIdx.x >> 5;
    const int lane = threadIdx.x & 31;
    const int nwarps = blockDim.x >> 5;

    for (int node = blockIdx.x * nwarps + warp; node < NN;
         node += gridDim.x * nwarps) {
        const float* h = g_agg2 + (size_t)node * F2;
        float acc[NC];
        #pragma unroll
        for (int c = 0; c < NC; c++) acc[c] = 0.f;

        for (int k = lane; k < F2; k += 32) {
            float v = fmaxf(h[k], 0.f);       // relu of layer 2
            #pragma unroll
            for (int c = 0; c < NC; c++)
                acc[c] += v * sW[k * NC + c];
        }
        #pragma unroll
        for (int off = 16; off > 0; off >>= 1)
            #pragma unroll
            for (int c = 0; c < NC; c++)
                acc[c] += __shfl_xor_sync(0xFFFFFFFFu, acc[c], off);

        if (lane == 0) {
            float l[NC];
            float m = -1e30f;
            #pragma unroll
            for (int c = 0; c < NC; c++) {
                l[c] = acc[c] + bc[c];
                m = fmaxf(m, l[c]);
            }
            float s = 0.f;
            #pragma unroll
            for (int c = 0; c < NC; c++) s += expf(l[c] - m);
            float ls = m + logf(s);
            #pragma unroll
            for (int c = 0; c < NC; c++)
                out[(size_t)node * NC + c] = l[c] - ls;
        }
    }
}

// ---------------- launch ----------------
extern "C" void kernel_launch(void* const* d_in, const int* in_sizes, int n_in,
                              void* d_out, int out_size) {
    const float* x   = (const float*)d_in[0];
    const void*  ei  = d_in[1];                 // int32 or int64, detected on device
    const float* W1  = (const float*)d_in[2];
    const float* b1  = (const float*)d_in[3];
    const float* W2  = (const float*)d_in[4];
    const float* b2  = (const float*)d_in[5];
    const float* Wc  = (const float*)d_in[6];
    const float* bc  = (const float*)d_in[7];
    float*       out = (float*)d_out;

    const int T = 256;

    // dtype detect + clean index arrays
    k_detect<<<1, 32>>>((const unsigned int*)ei);
    k_convert_idx<<<(NE + T - 1) / T, T>>>(ei);

    // degrees + norms
    k_deg_init<<<(NN + T - 1) / T, T>>>();
    k_deg_acc <<<(NE + T - 1) / T, T>>>();
    k_dinv    <<<(NN + T - 1) / T, T>>>();
    k_norm    <<<(NE + T - 1) / T, T>>>();

    // layer 1: h1 = x @ W1
    gemm64<1><<<dim3((NN + 63) / 64, (F1 + 63) / 64), T>>>(x, W1, NN, F1, F0);
    {
        int total4 = NN * (F1 / 4);
        k_agg_init<1><<<(total4 + T - 1) / T, T>>>(b1, F1 / 4, total4);
        long long tot = (long long)NE * (F1 / 4);
        k_scatter<1><<<(unsigned)((tot + T - 1) / T), T>>>(F1 / 4, tot);
    }

    // layer 2: h2 = relu(agg1) @ W2
    gemm64<2><<<dim3((NN + 63) / 64, (F2 + 63) / 64), T>>>(nullptr, W2, NN, F2, F1);
    {
        int total4 = NN * (F2 / 4);
        k_agg_init<2><<<(total4 + T - 1) / T, T>>>(b2, F2 / 4, total4);
        long long tot = (long long)NE * (F2 / 4);
        k_scatter<2><<<(unsigned)((tot + T - 1) / T), T>>>(F2 / 4, tot);
    }

    // classifier + log_softmax (relu fused on load)
    k_classify<<<6250, 256>>>(Wc, bc, out);
}

// round 9
// speedup vs baseline: 1.5214x; 1.5214x over previous
#include <cuda_runtime.h>

// Problem constants (fixed by the dataset)
static constexpr int NN  = 50000;   // nodes
static constexpr int NE  = 400000;  // edges
static constexpr int F0  = 128;     // input features
static constexpr int F1  = 256;     // hidden 1
static constexpr int F2  = 784;     // hidden 2
static constexpr int NC  = 10;      // classes

// ---------------- device scratch (static, allocation-free) ----------------
// Referenced ONLY from device code (host-side use => cudaErrorInvalidAddressSpace).
__device__ int   g_e64;                            // 1 if edge_index is int64
__device__ int   g_src32[NE];                      // clean int32 src indices
__device__ int   g_dst32[NE];                      // clean int32 dst indices
__device__ float g_dinv[NN];                       // deg accumulator -> deg^-1/2
__device__ float g_norm[NE];                       // edge norm
__device__ float g_h1  [(size_t)NN * F1];          // x @ W1
__device__ float g_agg1[(size_t)NN * F1];          // layer-1 pre-relu output
__device__ float g_h2  [(size_t)NN * F2];          // relu(agg1) @ W2
__device__ float g_agg2[(size_t)NN * F2];          // layer-2 pre-relu output

// ---------------- dtype detection + index materialization ----------------
__global__ void k_detect(const unsigned int* __restrict__ ei32) {
    if (threadIdx.x == 0 && blockIdx.x == 0) {
        int all0 = 1;
        #pragma unroll 1
        for (int i = 0; i < 64; i++)
            if (ei32[2 * i + 1] != 0u) { all0 = 0; break; }
        g_e64 = all0;
    }
}

__device__ __forceinline__ int edge_idx(const void* ei, int half, int e) {
    if (g_e64) return (int)((const long long*)ei)[(size_t)half * NE + e];
    return ((const int*)ei)[(size_t)half * NE + e];
}

__global__ void k_convert_idx(const void* __restrict__ ei) {
    int e = blockIdx.x * blockDim.x + threadIdx.x;
    if (e < NE) {
        g_src32[e] = edge_idx(ei, 0, e);
        g_dst32[e] = edge_idx(ei, 1, e);
    }
}

// ---------------- degree / norm kernels ----------------
__global__ void k_deg_init() {
    int i = blockIdx.x * blockDim.x + threadIdx.x;
    if (i < NN) g_dinv[i] = 1.0f;
}

__global__ void k_deg_acc() {
    int e = blockIdx.x * blockDim.x + threadIdx.x;
    if (e < NE) atomicAdd(&g_dinv[g_dst32[e]], 1.0f);
}

__global__ void k_dinv() {
    int i = blockIdx.x * blockDim.x + threadIdx.x;
    if (i < NN) g_dinv[i] = rsqrtf(g_dinv[i]);
}

__global__ void k_norm() {
    int e = blockIdx.x * blockDim.x + threadIdx.x;
    if (e < NE) g_norm[e] = g_dinv[g_src32[e]] * g_dinv[g_dst32[e]];
}

// ---------------- tf32 helpers ----------------
// cvt with tf32 destination requires a .b32 register operand (not .f32).
__device__ __forceinline__ unsigned tf32_cvt(float x) {
    unsigned r;
    asm("cvt.rna.tf32.f32 %0, %1;" : "=r"(r) : "f"(x));
    return r;
}

__device__ __forceinline__ void mma_tf32(float* d, const unsigned* a, const unsigned* b) {
    asm volatile(
        "mma.sync.aligned.m16n8k8.row.col.f32.tf32.tf32.f32 "
        "{%0,%1,%2,%3}, {%4,%5,%6,%7}, {%8,%9}, {%0,%1,%2,%3};"
        : "+f"(d[0]), "+f"(d[1]), "+f"(d[2]), "+f"(d[3])
        : "r"(a[0]), "r"(a[1]), "r"(a[2]), "r"(a[3]), "r"(b[0]), "r"(b[1]));
}

// ---------------- tensor-core GEMM (3xTF32 split, fp32-accurate) ----------------
// LAYER==1: g_h1 = A(x) @ W1;            M=NN, N=F1, K=F0
// LAYER==2: g_h2 = relu(g_agg1) @ W2;    M=NN, N=F2, K=F1
// BM=128, BN=64, BK=16; 256 threads = 8 warps in 4(M) x 2(N); warp tile 32x32.
template <int LAYER>
__global__ __launch_bounds__(256) void gemm_mma(const float* __restrict__ Aparam,
                                                const float* __restrict__ B,
                                                int M, int N, int K) {
    const float* __restrict__ A = (LAYER == 1) ? Aparam : g_agg1;
    float* __restrict__ C = (LAYER == 1) ? g_h1 : g_h2;

    constexpr int BM = 128, BN = 64, BK = 16;
    constexpr int ASTR = 20;   // A smem row stride (bank-conflict tuned)
    constexpr int BSTR = 72;   // B smem row stride

    __shared__ __align__(16) float As[BM][ASTR];
    __shared__ __align__(16) float Bs[BK][BSTR];

    const int tid  = threadIdx.x;
    const int bm   = blockIdx.x * BM;
    const int bn   = blockIdx.y * BN;
    const int warp = tid >> 5;
    const int lane = tid & 31;
    const int wm   = (warp & 3) * 32;   // warp M offset
    const int wn   = (warp >> 2) * 32;  // warp N offset
    const int qr   = lane >> 2;         // 0..7
    const int qc   = lane & 3;          // 0..3

    // global load mapping
    const int ar  = tid >> 1;           // A row 0..127
    const int ac8 = (tid & 1) * 8;      // A col offset {0,8}
    const int br  = tid >> 4;           // B k-row 0..15
    const int bc  = (tid & 15) * 4;     // B col offset

    float acc[2][4][4] = {};            // [mt][nt][reg]

    for (int k0 = 0; k0 < K; k0 += BK) {
        // ---- stage A tile ----
        float4 a0 = make_float4(0.f, 0.f, 0.f, 0.f);
        float4 a1 = make_float4(0.f, 0.f, 0.f, 0.f);
        if (bm + ar < M) {
            const float* ap = A + (size_t)(bm + ar) * K + k0 + ac8;
            a0 = *(const float4*)ap;
            a1 = *(const float4*)(ap + 4);
        }
        if (LAYER == 2) {
            a0.x = fmaxf(a0.x, 0.f); a0.y = fmaxf(a0.y, 0.f);
            a0.z = fmaxf(a0.z, 0.f); a0.w = fmaxf(a0.w, 0.f);
            a1.x = fmaxf(a1.x, 0.f); a1.y = fmaxf(a1.y, 0.f);
            a1.z = fmaxf(a1.z, 0.f); a1.w = fmaxf(a1.w, 0.f);
        }
        *(float4*)&As[ar][ac8]     = a0;
        *(float4*)&As[ar][ac8 + 4] = a1;

        // ---- stage B tile ----
        float4 b4 = make_float4(0.f, 0.f, 0.f, 0.f);
        if (bn + bc < N)    // N % 4 == 0 -> all-or-nothing
            b4 = *(const float4*)(B + (size_t)(k0 + br) * N + bn + bc);
        *(float4*)&Bs[br][bc] = b4;

        __syncthreads();

        #pragma unroll
        for (int kt = 0; kt < BK; kt += 8) {
            // A fragments (2 m-tiles), split hi/lo
            unsigned ah[2][4], al[2][4];
            #pragma unroll
            for (int mt = 0; mt < 2; mt++) {
                const int rb = wm + mt * 16;
                float ra[4];
                ra[0] = As[rb + qr    ][kt + qc    ];
                ra[1] = As[rb + qr + 8][kt + qc    ];
                ra[2] = As[rb + qr    ][kt + qc + 4];
                ra[3] = As[rb + qr + 8][kt + qc + 4];
                #pragma unroll
                for (int i = 0; i < 4; i++) {
                    unsigned h = tf32_cvt(ra[i]);
                    ah[mt][i] = h;
                    al[mt][i] = tf32_cvt(ra[i] - __uint_as_float(h));
                }
            }
            // B fragments (4 n-tiles), split hi/lo
            unsigned bh[4][2], bl[4][2];
            #pragma unroll
            for (int nt = 0; nt < 4; nt++) {
                const int col = wn + nt * 8 + qr;
                float rb0 = Bs[kt + qc    ][col];
                float rb1 = Bs[kt + qc + 4][col];
                unsigned h0 = tf32_cvt(rb0), h1 = tf32_cvt(rb1);
                bh[nt][0] = h0;
                bh[nt][1] = h1;
                bl[nt][0] = tf32_cvt(rb0 - __uint_as_float(h0));
                bl[nt][1] = tf32_cvt(rb1 - __uint_as_float(h1));
            }
            // 3xTF32: hi*hi + hi*lo + lo*hi
            #pragma unroll
            for (int mt = 0; mt < 2; mt++)
                #pragma unroll
                for (int nt = 0; nt < 4; nt++) {
                    mma_tf32(acc[mt][nt], ah[mt], bh[nt]);
                    mma_tf32(acc[mt][nt], ah[mt], bl[nt]);
                    mma_tf32(acc[mt][nt], al[mt], bh[nt]);
                }
        }
        __syncthreads();
    }

    // ---- store C ----
    #pragma unroll
    for (int mt = 0; mt < 2; mt++) {
        const int r0 = bm + wm + mt * 16 + qr;
        #pragma unroll
        for (int nt = 0; nt < 4; nt++) {
            const int col = bn + wn + nt * 8 + qc * 2;
            if (col < N) {
                if (r0 < M)
                    *(float2*)(C + (size_t)r0 * N + col) =
                        make_float2(acc[mt][nt][0], acc[mt][nt][1]);
                if (r0 + 8 < M)
                    *(float2*)(C + (size_t)(r0 + 8) * N + col) =
                        make_float2(acc[mt][nt][2], acc[mt][nt][3]);
            }
        }
    }
}

// ---------------- aggregation init: agg = h * self_norm + bias ----------------
template <int LAYER>
__global__ void k_agg_init(const float* __restrict__ bias, int F4, int total4) {
    const float* __restrict__ h = (LAYER == 1) ? g_h1 : g_h2;
    float* __restrict__ agg = (LAYER == 1) ? g_agg1 : g_agg2;

    int idx = blockIdx.x * blockDim.x + threadIdx.x;
    if (idx >= total4) return;
    int node = idx / F4;
    int q = idx - node * F4;
    float sn = g_dinv[node];
    sn *= sn;                       // self_norm = 1/deg
    float4 v = *(const float4*)(h + (size_t)idx * 4);
    float4 b = ((const float4*)bias)[q];
    v.x = v.x * sn + b.x; v.y = v.y * sn + b.y;
    v.z = v.z * sn + b.z; v.w = v.w * sn + b.w;
    *(float4*)(agg + (size_t)idx * 4) = v;
}

// ---------------- edge scatter: agg[dst] += h[src] * norm (vector red) ----------------
template <int LAYER>
__global__ void k_scatter(int F4, long long total) {
    const float* __restrict__ h = (LAYER == 1) ? g_h1 : g_h2;
    float* __restrict__ agg = (LAYER == 1) ? g_agg1 : g_agg2;

    long long idx = (long long)blockIdx.x * blockDim.x + threadIdx.x;
    if (idx >= total) return;
    int e = (int)(idx / F4);
    int q = (int)(idx - (long long)e * F4);
    int s = g_src32[e];
    int d = g_dst32[e];
    float w = g_norm[e];
    float4 v = *(const float4*)(h + (size_t)s * (F4 * 4) + q * 4);
    float* o = agg + (size_t)d * (F4 * 4) + q * 4;
    asm volatile("red.global.add.v4.f32 [%0], {%1,%2,%3,%4};"
                 :: "l"(o), "f"(v.x * w), "f"(v.y * w), "f"(v.z * w), "f"(v.w * w)
                 : "memory");
}

// ---------------- classifier + log_softmax (warp per node) ----------------
__global__ void k_classify(const float* __restrict__ Wc, const float* __restrict__ bc,
                           float* __restrict__ out) {
    __shared__ float sW[F2 * NC];  // 31360 B
    for (int i = threadIdx.x; i < F2 * NC; i += blockDim.x)
        sW[i] = Wc[i];
    __syncthreads();

    const int warp = threadIdx.x >> 5;
    const int lane = threadIdx.x & 31;
    const int nwarps = blockDim.x >> 5;

    for (int node = blockIdx.x * nwarps + warp; node < NN;
         node += gridDim.x * nwarps) {
        const float* h = g_agg2 + (size_t)node * F2;
        float acc[NC];
        #pragma unroll
        for (int c = 0; c < NC; c++) acc[c] = 0.f;

        for (int k = lane; k < F2; k += 32) {
            float v = fmaxf(h[k], 0.f);       // relu of layer 2
            #pragma unroll
            for (int c = 0; c < NC; c++)
                acc[c] += v * sW[k * NC + c];
        }
        #pragma unroll
        for (int off = 16; off > 0; off >>= 1)
            #pragma unroll
            for (int c = 0; c < NC; c++)
                acc[c] += __shfl_xor_sync(0xFFFFFFFFu, acc[c], off);

        if (lane == 0) {
            float l[NC];
            float m = -1e30f;
            #pragma unroll
            for (int c = 0; c < NC; c++) {
                l[c] = acc[c] + bc[c];
                m = fmaxf(m, l[c]);
            }
            float s = 0.f;
            #pragma unroll
            for (int c = 0; c < NC; c++) s += expf(l[c] - m);
            float ls = m + logf(s);
            #pragma unroll
            for (int c = 0; c < NC; c++)
                out[(size_t)node * NC + c] = l[c] - ls;
        }
    }
}

// ---------------- launch ----------------
extern "C" void kernel_launch(void* const* d_in, const int* in_sizes, int n_in,
                              void* d_out, int out_size) {
    const float* x   = (const float*)d_in[0];
    const void*  ei  = d_in[1];                 // int32 or int64, detected on device
    const float* W1  = (const float*)d_in[2];
    const float* b1  = (const float*)d_in[3];
    const float* W2  = (const float*)d_in[4];
    const float* b2  = (const float*)d_in[5];
    const float* Wc  = (const float*)d_in[6];
    const float* bc  = (const float*)d_in[7];
    float*       out = (float*)d_out;

    const int T = 256;

    // dtype detect + clean index arrays
    k_detect<<<1, 32>>>((const unsigned int*)ei);
    k_convert_idx<<<(NE + T - 1) / T, T>>>(ei);

    // degrees + norms
    k_deg_init<<<(NN + T - 1) / T, T>>>();
    k_deg_acc <<<(NE + T - 1) / T, T>>>();
    k_dinv    <<<(NN + T - 1) / T, T>>>();
    k_norm    <<<(NE + T - 1) / T, T>>>();

    // layer 1: h1 = x @ W1
    gemm_mma<1><<<dim3((NN + 127) / 128, (F1 + 63) / 64), T>>>(x, W1, NN, F1, F0);
    {
        int total4 = NN * (F1 / 4);
        k_agg_init<1><<<(total4 + T - 1) / T, T>>>(b1, F1 / 4, total4);
        long long tot = (long long)NE * (F1 / 4);
        k_scatter<1><<<(unsigned)((tot + T - 1) / T), T>>>(F1 / 4, tot);
    }

    // layer 2: h2 = relu(agg1) @ W2
    gemm_mma<2><<<dim3((NN + 127) / 128, (F2 + 63) / 64), T>>>(nullptr, W2, NN, F2, F1);
    {
        int total4 = NN * (F2 / 4);
        k_agg_init<2><<<(total4 + T - 1) / T, T>>>(b2, F2 / 4, total4);
        long long tot = (long long)NE * (F2 / 4);
        k_scatter<2><<<(unsigned)((tot + T - 1) / T), T>>>(F2 / 4, tot);
    }

    // classifier + log_softmax (relu fused on load)
    k_classify<<<6250, 256>>>(Wc, bc, out);
}

// round 11
// speedup vs baseline: 2.4303x; 1.5974x over previous
#include <cuda_runtime.h>

// Problem constants (fixed by the dataset)
static constexpr int NN  = 50000;   // nodes
static constexpr int NE  = 400000;  // edges
static constexpr int F0  = 128;     // input features
static constexpr int F1  = 256;     // hidden 1
static constexpr int F2  = 784;     // hidden 2
static constexpr int NC  = 10;      // classes

// ---------------- device scratch (static, allocation-free) ----------------
// Referenced ONLY from device code (host-side use => cudaErrorInvalidAddressSpace).
// Pipeline (uses S(hW) = (S h)W, bias/relu folded into GEMM epilogue):
//   g_aggx = S x                  (128-dim aggregation, L2-resident)
//   g_l1   = relu(g_aggx @ W1+b1)
//   g_aggh = S g_l1               (256-dim aggregation, L2-resident)
//   g_l2   = relu(g_aggh @ W2+b2)
//   out    = log_softmax(g_l2 @ Wc + bc)
__device__ int   g_e64;                            // 1 if edge_index is int64
__device__ int   g_src32[NE];                      // clean int32 src indices
__device__ int   g_dst32[NE];                      // clean int32 dst indices
__device__ float g_dinv[NN];                       // deg accumulator -> deg^-1/2
__device__ float g_norm[NE];                       // edge norm
__device__ float g_aggx[(size_t)NN * F0];          // S x
__device__ float g_l1  [(size_t)NN * F1];          // relu(aggx@W1+b1)
__device__ float g_aggh[(size_t)NN * F1];          // S l1
__device__ float g_l2  [(size_t)NN * F2];          // relu(aggh@W2+b2)

// ---------------- dtype detection + index materialization ----------------
__global__ void k_detect(const unsigned int* __restrict__ ei32) {
    if (threadIdx.x == 0 && blockIdx.x == 0) {
        int all0 = 1;
        #pragma unroll 1
        for (int i = 0; i < 64; i++)
            if (ei32[2 * i + 1] != 0u) { all0 = 0; break; }
        g_e64 = all0;
    }
}

__device__ __forceinline__ int edge_idx(const void* ei, int half, int e) {
    if (g_e64) return (int)((const long long*)ei)[(size_t)half * NE + e];
    return ((const int*)ei)[(size_t)half * NE + e];
}

__global__ void k_convert_idx(const void* __restrict__ ei) {
    int e = blockIdx.x * blockDim.x + threadIdx.x;
    if (e < NE) {
        g_src32[e] = edge_idx(ei, 0, e);
        g_dst32[e] = edge_idx(ei, 1, e);
    }
}

// ---------------- degree / norm kernels ----------------
__global__ void k_deg_init() {
    int i = blockIdx.x * blockDim.x + threadIdx.x;
    if (i < NN) g_dinv[i] = 1.0f;
}

__global__ void k_deg_acc() {
    int e = blockIdx.x * blockDim.x + threadIdx.x;
    if (e < NE) atomicAdd(&g_dinv[g_dst32[e]], 1.0f);
}

__global__ void k_dinv() {
    int i = blockIdx.x * blockDim.x + threadIdx.x;
    if (i < NN) g_dinv[i] = rsqrtf(g_dinv[i]);
}

__global__ void k_norm() {
    int e = blockIdx.x * blockDim.x + threadIdx.x;
    if (e < NE) g_norm[e] = g_dinv[g_src32[e]] * g_dinv[g_dst32[e]];
}

// ---------------- aggregation init: agg = h * self_norm ----------------
// LAYER==1: agg=g_aggx, h=x(param), F=F0.  LAYER==2: agg=g_aggh, h=g_l1, F=F1.
template <int LAYER>
__global__ void k_agg_init(const float* __restrict__ hparam, int F4, int total4) {
    const float* __restrict__ h = (LAYER == 1) ? hparam : g_l1;
    float* __restrict__ agg = (LAYER == 1) ? g_aggx : g_aggh;

    int idx = blockIdx.x * blockDim.x + threadIdx.x;
    if (idx >= total4) return;
    int node = idx / F4;
    float sn = g_dinv[node];
    sn *= sn;                       // self_norm = 1/deg
    float4 v = *(const float4*)(h + (size_t)idx * 4);
    v.x *= sn; v.y *= sn; v.z *= sn; v.w *= sn;
    *(float4*)(agg + (size_t)idx * 4) = v;
}

// ---------------- edge scatter: agg[dst] += h[src] * norm (vector red) ----------------
template <int LAYER>
__global__ void k_scatter(const float* __restrict__ hparam, int F4, long long total) {
    const float* __restrict__ h = (LAYER == 1) ? hparam : g_l1;
    float* __restrict__ agg = (LAYER == 1) ? g_aggx : g_aggh;

    long long idx = (long long)blockIdx.x * blockDim.x + threadIdx.x;
    if (idx >= total) return;
    int e = (int)(idx / F4);
    int q = (int)(idx - (long long)e * F4);
    int s = g_src32[e];
    int d = g_dst32[e];
    float w = g_norm[e];
    float4 v = *(const float4*)(h + (size_t)s * (F4 * 4) + q * 4);
    float* o = agg + (size_t)d * (F4 * 4) + q * 4;
    asm volatile("red.global.add.v4.f32 [%0], {%1,%2,%3,%4};"
                 :: "l"(o), "f"(v.x * w), "f"(v.y * w), "f"(v.z * w), "f"(v.w * w)
                 : "memory");
}

// ---------------- tf32 helpers ----------------
__device__ __forceinline__ unsigned tf32_cvt(float x) {
    unsigned r;
    asm("cvt.rna.tf32.f32 %0, %1;" : "=r"(r) : "f"(x));
    return r;
}

__device__ __forceinline__ void mma_tf32(float* d, const unsigned* a, const unsigned* b) {
    asm volatile(
        "mma.sync.aligned.m16n8k8.row.col.f32.tf32.tf32.f32 "
        "{%0,%1,%2,%3}, {%4,%5,%6,%7}, {%8,%9}, {%0,%1,%2,%3};"
        : "+f"(d[0]), "+f"(d[1]), "+f"(d[2]), "+f"(d[3])
        : "r"(a[0]), "r"(a[1]), "r"(a[2]), "r"(a[3]), "r"(b[0]), "r"(b[1]));
}

// ---------------- tensor-core GEMM (3xTF32) with bias+relu epilogue ----------------
// LAYER==1: g_l1 = relu(g_aggx @ W1 + b1);  M=NN, N=F1, K=F0
// LAYER==2: g_l2 = relu(g_aggh @ W2 + b2);  M=NN, N=F2, K=F1
// BM=128, BN=64, BK=16; 256 threads = 8 warps in 4(M) x 2(N); warp tile 32x32.
template <int LAYER>
__global__ __launch_bounds__(256) void gemm_mma(const float* __restrict__ B,
                                                const float* __restrict__ bias,
                                                int M, int N, int K) {
    const float* __restrict__ A = (LAYER == 1) ? g_aggx : g_aggh;
    float* __restrict__ C = (LAYER == 1) ? g_l1 : g_l2;

    constexpr int BM = 128, BN = 64, BK = 16;
    constexpr int ASTR = 20;   // A smem row stride (bank-conflict tuned)
    constexpr int BSTR = 72;   // B smem row stride

    __shared__ __align__(16) float As[BM][ASTR];
    __shared__ __align__(16) float Bs[BK][BSTR];

    const int tid  = threadIdx.x;
    const int bm   = blockIdx.x * BM;
    const int bn   = blockIdx.y * BN;
    const int warp = tid >> 5;
    const int lane = tid & 31;
    const int wm   = (warp & 3) * 32;   // warp M offset
    const int wn   = (warp >> 2) * 32;  // warp N offset
    const int qr   = lane >> 2;         // 0..7
    const int qc   = lane & 3;          // 0..3

    // global load mapping
    const int ar  = tid >> 1;           // A row 0..127
    const int ac8 = (tid & 1) * 8;      // A col offset {0,8}
    const int br  = tid >> 4;           // B k-row 0..15
    const int bc  = (tid & 15) * 4;     // B col offset

    float acc[2][4][4] = {};            // [mt][nt][reg]

    for (int k0 = 0; k0 < K; k0 += BK) {
        // ---- stage A tile ----
        float4 a0 = make_float4(0.f, 0.f, 0.f, 0.f);
        float4 a1 = make_float4(0.f, 0.f, 0.f, 0.f);
        if (bm + ar < M) {
            const float* ap = A + (size_t)(bm + ar) * K + k0 + ac8;
            a0 = *(const float4*)ap;
            a1 = *(const float4*)(ap + 4);
        }
        *(float4*)&As[ar][ac8]     = a0;
        *(float4*)&As[ar][ac8 + 4] = a1;

        // ---- stage B tile ----
        float4 b4 = make_float4(0.f, 0.f, 0.f, 0.f);
        if (bn + bc < N)    // N % 4 == 0 -> all-or-nothing
            b4 = *(const float4*)(B + (size_t)(k0 + br) * N + bn + bc);
        *(float4*)&Bs[br][bc] = b4;

        __syncthreads();

        #pragma unroll
        for (int kt = 0; kt < BK; kt += 8) {
            // A fragments (2 m-tiles), split hi/lo
            unsigned ah[2][4], al[2][4];
            #pragma unroll
            for (int mt = 0; mt < 2; mt++) {
                const int rb = wm + mt * 16;
                float ra[4];
                ra[0] = As[rb + qr    ][kt + qc    ];
                ra[1] = As[rb + qr + 8][kt + qc    ];
                ra[2] = As[rb + qr    ][kt + qc + 4];
                ra[3] = As[rb + qr + 8][kt + qc + 4];
                #pragma unroll
                for (int i = 0; i < 4; i++) {
                    unsigned h = tf32_cvt(ra[i]);
                    ah[mt][i] = h;
                    al[mt][i] = tf32_cvt(ra[i] - __uint_as_float(h));
                }
            }
            // B fragments (4 n-tiles), split hi/lo
            unsigned bh[4][2], bl[4][2];
            #pragma unroll
            for (int nt = 0; nt < 4; nt++) {
                const int col = wn + nt * 8 + qr;
                float rb0 = Bs[kt + qc    ][col];
                float rb1 = Bs[kt + qc + 4][col];
                unsigned h0 = tf32_cvt(rb0), h1 = tf32_cvt(rb1);
                bh[nt][0] = h0;
                bh[nt][1] = h1;
                bl[nt][0] = tf32_cvt(rb0 - __uint_as_float(h0));
                bl[nt][1] = tf32_cvt(rb1 - __uint_as_float(h1));
            }
            // 3xTF32: hi*hi + hi*lo + lo*hi
            #pragma unroll
            for (int mt = 0; mt < 2; mt++)
                #pragma unroll
                for (int nt = 0; nt < 4; nt++) {
                    mma_tf32(acc[mt][nt], ah[mt], bh[nt]);
                    mma_tf32(acc[mt][nt], ah[mt], bl[nt]);
                    mma_tf32(acc[mt][nt], al[mt], bh[nt]);
                }
        }
        __syncthreads();
    }

    // ---- store C with bias + relu epilogue ----
    #pragma unroll
    for (int mt = 0; mt < 2; mt++) {
        const int r0 = bm + wm + mt * 16 + qr;
        #pragma unroll
        for (int nt = 0; nt < 4; nt++) {
            const int col = bn + wn + nt * 8 + qc * 2;
            if (col < N) {
                float2 bv = *(const float2*)(bias + col);
                float v0 = fmaxf(acc[mt][nt][0] + bv.x, 0.f);
                float v1 = fmaxf(acc[mt][nt][1] + bv.y, 0.f);
                float v2 = fmaxf(acc[mt][nt][2] + bv.x, 0.f);
                float v3 = fmaxf(acc[mt][nt][3] + bv.y, 0.f);
                if (r0 < M)
                    *(float2*)(C + (size_t)r0 * N + col) = make_float2(v0, v1);
                if (r0 + 8 < M)
                    *(float2*)(C + (size_t)(r0 + 8) * N + col) = make_float2(v2, v3);
            }
        }
    }
}

// ---------------- classifier + log_softmax (warp per node) ----------------
// g_l2 is already relu'd with bias applied.
__global__ void k_classify(const float* __restrict__ Wc, const float* __restrict__ bc,
                           float* __restrict__ out) {
    __shared__ float sW[F2 * NC];  // 31360 B
    for (int i = threadIdx.x; i < F2 * NC; i += blockDim.x)
        sW[i] = Wc[i];
    __syncthreads();

    const int warp = threadIdx.x >> 5;
    const int lane = threadIdx.x & 31;
    const int nwarps = blockDim.x >> 5;

    for (int node = blockIdx.x * nwarps + warp; node < NN;
         node += gridDim.x * nwarps) {
        const float* h = g_l2 + (size_t)node * F2;
        float acc[NC];
        #pragma unroll
        for (int c = 0; c < NC; c++) acc[c] = 0.f;

        for (int k = lane; k < F2; k += 32) {
            float v = h[k];
            #pragma unroll
            for (int c = 0; c < NC; c++)
                acc[c] += v * sW[k * NC + c];
        }
        #pragma unroll
        for (int off = 16; off > 0; off >>= 1)
            #pragma unroll
            for (int c = 0; c < NC; c++)
                acc[c] += __shfl_xor_sync(0xFFFFFFFFu, acc[c], off);

        if (lane == 0) {
            float l[NC];
            float m = -1e30f;
            #pragma unroll
            for (int c = 0; c < NC; c++) {
                l[c] = acc[c] + bc[c];
                m = fmaxf(m, l[c]);
            }
            float s = 0.f;
            #pragma unroll
            for (int c = 0; c < NC; c++) s += expf(l[c] - m);
            float ls = m + logf(s);
            #pragma unroll
            for (int c = 0; c < NC; c++)
                out[(size_t)node * NC + c] = l[c] - ls;
        }
    }
}

// ---------------- launch ----------------
extern "C" void kernel_launch(void* const* d_in, const int* in_sizes, int n_in,
                              void* d_out, int out_size) {
    const float* x   = (const float*)d_in[0];
    const void*  ei  = d_in[1];                 // int32 or int64, detected on device
    const float* W1  = (const float*)d_in[2];
    const float* b1  = (const float*)d_in[3];
    const float* W2  = (const float*)d_in[4];
    const float* b2  = (const float*)d_in[5];
    const float* Wc  = (const float*)d_in[6];
    const float* bc  = (const float*)d_in[7];
    float*       out = (float*)d_out;

    const int T = 256;

    // dtype detect + clean index arrays
    k_detect<<<1, 32>>>((const unsigned int*)ei);
    k_convert_idx<<<(NE + T - 1) / T, T>>>(ei);

    // degrees + norms
    k_deg_init<<<(NN + T - 1) / T, T>>>();
    k_deg_acc <<<(NE + T - 1) / T, T>>>();
    k_dinv    <<<(NN + T - 1) / T, T>>>();
    k_norm    <<<(NE + T - 1) / T, T>>>();

    // aggx = S x   (128-dim aggregation, L2-resident)
    {
        int total4 = NN * (F0 / 4);
        k_agg_init<1><<<(total4 + T - 1) / T, T>>>(x, F0 / 4, total4);
        long long tot = (long long)NE * (F0 / 4);
        k_scatter<1><<<(unsigned)((tot + T - 1) / T), T>>>(x, F0 / 4, tot);
    }

    // l1 = relu(aggx @ W1 + b1)
    gemm_mma<1><<<dim3((NN + 127) / 128, (F1 + 63) / 64), T>>>(W1, b1, NN, F1, F0);

    // aggh = S l1   (256-dim aggregation, L2-resident)
    {
        int total4 = NN * (F1 / 4);
        k_agg_init<2><<<(total4 + T - 1) / T, T>>>(nullptr, F1 / 4, total4);
        long long tot = (long long)NE * (F1 / 4);
        k_scatter<2><<<(unsigned)((tot + T - 1) / T), T>>>(nullptr, F1 / 4, tot);
    }

    // l2 = relu(aggh @ W2 + b2)
    gemm_mma<2><<<dim3((NN + 127) / 128, (F2 + 63) / 64), T>>>(W2, b2, NN, F2, F1);

    // classifier + log_softmax
    k_classify<<<6250, 256>>>(Wc, bc, out);
}

// round 12
// speedup vs baseline: 2.5694x; 1.0572x over previous
#include <cuda_runtime.h>

// Problem constants (fixed by the dataset)
static constexpr int NN  = 50000;   // nodes
static constexpr int NE  = 400000;  // edges
static constexpr int F0  = 128;     // input features
static constexpr int F1  = 256;     // hidden 1
static constexpr int F2  = 784;     // hidden 2
static constexpr int NC  = 10;      // classes

// ---------------- device scratch (static, allocation-free) ----------------
// Referenced ONLY from device code (host-side use => cudaErrorInvalidAddressSpace).
// Pipeline (S(hW) = (S h)W; bias/relu folded into GEMM epilogue; classifier
// fused into GEMM2 epilogue as atomic partial logits):
//   g_aggx   = S x
//   g_l1     = relu(g_aggx @ W1 + b1)
//   g_aggh   = S g_l1
//   g_logits = bc + sum_tiles relu(g_aggh @ W2 + b2) @ Wc   (atomic accumulate)
//   out      = log_softmax(g_logits)
__device__ int   g_e64;                            // 1 if edge_index is int64
__device__ int   g_src32[NE];                      // clean int32 src indices
__device__ int   g_dst32[NE];                      // clean int32 dst indices
__device__ float g_dinv[NN];                       // deg accumulator -> deg^-1/2
__device__ float g_norm[NE];                       // edge norm
__device__ float g_aggx[(size_t)NN * F0];          // S x
__device__ float g_l1  [(size_t)NN * F1];          // relu(aggx@W1+b1)
__device__ float g_aggh[(size_t)NN * F1];          // S l1
__device__ float g_logits[(size_t)NN * NC];        // fused classifier accumulator

// ---------------- dtype detection + index materialization ----------------
__global__ void k_detect(const unsigned int* __restrict__ ei32) {
    if (threadIdx.x == 0 && blockIdx.x == 0) {
        int all0 = 1;
        #pragma unroll 1
        for (int i = 0; i < 64; i++)
            if (ei32[2 * i + 1] != 0u) { all0 = 0; break; }
        g_e64 = all0;
    }
}

__device__ __forceinline__ int edge_idx(const void* ei, int half, int e) {
    if (g_e64) return (int)((const long long*)ei)[(size_t)half * NE + e];
    return ((const int*)ei)[(size_t)half * NE + e];
}

__global__ void k_convert_idx(const void* __restrict__ ei) {
    int e = blockIdx.x * blockDim.x + threadIdx.x;
    if (e < NE) {
        g_src32[e] = edge_idx(ei, 0, e);
        g_dst32[e] = edge_idx(ei, 1, e);
    }
}

// ---------------- degree / norm kernels ----------------
__global__ void k_deg_init() {
    int i = blockIdx.x * blockDim.x + threadIdx.x;
    if (i < NN) g_dinv[i] = 1.0f;
}

__global__ void k_deg_acc() {
    int e = blockIdx.x * blockDim.x + threadIdx.x;
    if (e < NE) atomicAdd(&g_dinv[g_dst32[e]], 1.0f);
}

__global__ void k_dinv() {
    int i = blockIdx.x * blockDim.x + threadIdx.x;
    if (i < NN) g_dinv[i] = rsqrtf(g_dinv[i]);
}

__global__ void k_norm() {
    int e = blockIdx.x * blockDim.x + threadIdx.x;
    if (e < NE) g_norm[e] = g_dinv[g_src32[e]] * g_dinv[g_dst32[e]];
}

// ---------------- aggregation init: agg = h * self_norm ----------------
template <int LAYER>
__global__ void k_agg_init(const float* __restrict__ hparam, int F4, int total4) {
    const float* __restrict__ h = (LAYER == 1) ? hparam : g_l1;
    float* __restrict__ agg = (LAYER == 1) ? g_aggx : g_aggh;

    int idx = blockIdx.x * blockDim.x + threadIdx.x;
    if (idx >= total4) return;
    int node = idx / F4;
    float sn = g_dinv[node];
    sn *= sn;                       // self_norm = 1/deg
    float4 v = *(const float4*)(h + (size_t)idx * 4);
    v.x *= sn; v.y *= sn; v.z *= sn; v.w *= sn;
    *(float4*)(agg + (size_t)idx * 4) = v;
}

// ---------------- edge scatter: agg[dst] += h[src] * norm (vector red) ----------------
template <int LAYER>
__global__ void k_scatter(const float* __restrict__ hparam, int F4, long long total) {
    const float* __restrict__ h = (LAYER == 1) ? hparam : g_l1;
    float* __restrict__ agg = (LAYER == 1) ? g_aggx : g_aggh;

    long long idx = (long long)blockIdx.x * blockDim.x + threadIdx.x;
    if (idx >= total) return;
    int e = (int)(idx / F4);
    int q = (int)(idx - (long long)e * F4);
    int s = g_src32[e];
    int d = g_dst32[e];
    float w = g_norm[e];
    float4 v = *(const float4*)(h + (size_t)s * (F4 * 4) + q * 4);
    float* o = agg + (size_t)d * (F4 * 4) + q * 4;
    asm volatile("red.global.add.v4.f32 [%0], {%1,%2,%3,%4};"
                 :: "l"(o), "f"(v.x * w), "f"(v.y * w), "f"(v.z * w), "f"(v.w * w)
                 : "memory");
}

// ---------------- tf32 helpers ----------------
__device__ __forceinline__ unsigned tf32_cvt(float x) {
    unsigned r;
    asm("cvt.rna.tf32.f32 %0, %1;" : "=r"(r) : "f"(x));
    return r;
}

__device__ __forceinline__ void mma_tf32(float* d, const unsigned* a, const unsigned* b) {
    asm volatile(
        "mma.sync.aligned.m16n8k8.row.col.f32.tf32.tf32.f32 "
        "{%0,%1,%2,%3}, {%4,%5,%6,%7}, {%8,%9}, {%0,%1,%2,%3};"
        : "+f"(d[0]), "+f"(d[1]), "+f"(d[2]), "+f"(d[3])
        : "r"(a[0]), "r"(a[1]), "r"(a[2]), "r"(a[3]), "r"(b[0]), "r"(b[1]));
}

// ---------------- tensor-core GEMM (3xTF32, hi/lo pre-split in smem) ----------------
// LAYER==1: g_l1 = relu(g_aggx @ W1 + b1); store to gmem.     M=NN, N=F1, K=F0
// LAYER==2: relu(g_aggh @ W2 + b2) @ Wc -> atomic g_logits.   M=NN, N=F2, K=F1
// BM=128, BN=64, BK=16; 256 threads = 8 warps in 4(M) x 2(N); warp tile 32x32.
template <int LAYER>
__global__ __launch_bounds__(256) void gemm_mma(const float* __restrict__ B,
                                                const float* __restrict__ bias,
                                                const float* __restrict__ Wc,
                                                int M, int N, int K) {
    const float* __restrict__ A = (LAYER == 1) ? g_aggx : g_aggh;

    constexpr int BM = 128, BN = 64, BK = 16;
    constexpr int ASTR = 20;   // conflict-free for fragment reads (verified bank map)
    constexpr int BSTR = 72;

    __shared__ __align__(16) unsigned As_h[BM][ASTR];
    __shared__ __align__(16) unsigned As_l[BM][ASTR];
    __shared__ __align__(16) unsigned Bs_h[BK][BSTR];
    __shared__ __align__(16) unsigned Bs_l[BK][BSTR];
    __shared__ float sWc[(LAYER == 2) ? BN * NC : 1];   // Wc slice for fused classifier

    const int tid  = threadIdx.x;
    const int bm   = blockIdx.x * BM;
    const int bn   = blockIdx.y * BN;
    const int warp = tid >> 5;
    const int lane = tid & 31;
    const int wm   = (warp & 3) * 32;   // warp M offset
    const int wn   = (warp >> 2) * 32;  // warp N offset
    const int qr   = lane >> 2;         // 0..7
    const int qc   = lane & 3;          // 0..3

    // global load mapping
    const int ar  = tid >> 1;           // A row 0..127
    const int ac8 = (tid & 1) * 8;      // A col offset {0,8}
    const int br  = tid >> 4;           // B k-row 0..15
    const int bc  = (tid & 15) * 4;     // B col offset

    if (LAYER == 2) {                   // stage Wc slice [BN rows x NC]
        for (int i = tid; i < BN * NC; i += 256) {
            int row = bn + i / NC;
            sWc[i] = (row < F2) ? Wc[(size_t)row * NC + (i % NC)] : 0.f;
        }
    }

    float acc[2][4][4] = {};            // [mt][nt][reg]

    for (int k0 = 0; k0 < K; k0 += BK) {
        // ---- stage A tile, hi/lo pre-split ----
        float av[8];
        {
            float4 a0 = make_float4(0.f, 0.f, 0.f, 0.f);
            float4 a1 = make_float4(0.f, 0.f, 0.f, 0.f);
            if (bm + ar < M) {
                const float* ap = A + (size_t)(bm + ar) * K + k0 + ac8;
                a0 = *(const float4*)ap;
                a1 = *(const float4*)(ap + 4);
            }
            av[0] = a0.x; av[1] = a0.y; av[2] = a0.z; av[3] = a0.w;
            av[4] = a1.x; av[5] = a1.y; av[6] = a1.z; av[7] = a1.w;
        }
        unsigned hh[8], ll[8];
        #pragma unroll
        for (int i = 0; i < 8; i++) {
            hh[i] = tf32_cvt(av[i]);
            ll[i] = tf32_cvt(av[i] - __uint_as_float(hh[i]));
        }
        *(uint4*)&As_h[ar][ac8]     = make_uint4(hh[0], hh[1], hh[2], hh[3]);
        *(uint4*)&As_h[ar][ac8 + 4] = make_uint4(hh[4], hh[5], hh[6], hh[7]);
        *(uint4*)&As_l[ar][ac8]     = make_uint4(ll[0], ll[1], ll[2], ll[3]);
        *(uint4*)&As_l[ar][ac8 + 4] = make_uint4(ll[4], ll[5], ll[6], ll[7]);

        // ---- stage B tile, hi/lo pre-split ----
        {
            float4 b4 = make_float4(0.f, 0.f, 0.f, 0.f);
            if (bn + bc < N)    // N % 4 == 0 -> all-or-nothing
                b4 = *(const float4*)(B + (size_t)(k0 + br) * N + bn + bc);
            unsigned bhh[4], bll[4];
            float bv[4] = {b4.x, b4.y, b4.z, b4.w};
            #pragma unroll
            for (int i = 0; i < 4; i++) {
                bhh[i] = tf32_cvt(bv[i]);
                bll[i] = tf32_cvt(bv[i] - __uint_as_float(bhh[i]));
            }
            *(uint4*)&Bs_h[br][bc] = make_uint4(bhh[0], bhh[1], bhh[2], bhh[3]);
            *(uint4*)&Bs_l[br][bc] = make_uint4(bll[0], bll[1], bll[2], bll[3]);
        }

        __syncthreads();

        #pragma unroll
        for (int kt = 0; kt < BK; kt += 8) {
            unsigned ah[2][4], al[2][4];
            #pragma unroll
            for (int mt = 0; mt < 2; mt++) {
                const int rb = wm + mt * 16;
                ah[mt][0] = As_h[rb + qr    ][kt + qc    ];
                ah[mt][1] = As_h[rb + qr + 8][kt + qc    ];
                ah[mt][2] = As_h[rb + qr    ][kt + qc + 4];
                ah[mt][3] = As_h[rb + qr + 8][kt + qc + 4];
                al[mt][0] = As_l[rb + qr    ][kt + qc    ];
                al[mt][1] = As_l[rb + qr + 8][kt + qc    ];
                al[mt][2] = As_l[rb + qr    ][kt + qc + 4];
                al[mt][3] = As_l[rb + qr + 8][kt + qc + 4];
            }
            unsigned bh[4][2], bl[4][2];
            #pragma unroll
            for (int nt = 0; nt < 4; nt++) {
                const int col = wn + nt * 8 + qr;
                bh[nt][0] = Bs_h[kt + qc    ][col];
                bh[nt][1] = Bs_h[kt + qc + 4][col];
                bl[nt][0] = Bs_l[kt + qc    ][col];
                bl[nt][1] = Bs_l[kt + qc + 4][col];
            }
            #pragma unroll
            for (int mt = 0; mt < 2; mt++)
                #pragma unroll
                for (int nt = 0; nt < 4; nt++) {
                    mma_tf32(acc[mt][nt], ah[mt], bh[nt]);
                    mma_tf32(acc[mt][nt], ah[mt], bl[nt]);
                    mma_tf32(acc[mt][nt], al[mt], bh[nt]);
                }
        }
        __syncthreads();
    }

    if (LAYER == 1) {
        // ---- store C with bias + relu epilogue ----
        #pragma unroll
        for (int mt = 0; mt < 2; mt++) {
            const int r0 = bm + wm + mt * 16 + qr;
            #pragma unroll
            for (int nt = 0; nt < 4; nt++) {
                const int col = bn + wn + nt * 8 + qc * 2;
                if (col < N) {
                    float2 bv = *(const float2*)(bias + col);
                    float v0 = fmaxf(acc[mt][nt][0] + bv.x, 0.f);
                    float v1 = fmaxf(acc[mt][nt][1] + bv.y, 0.f);
                    float v2 = fmaxf(acc[mt][nt][2] + bv.x, 0.f);
                    float v3 = fmaxf(acc[mt][nt][3] + bv.y, 0.f);
                    if (r0 < M)
                        *(float2*)(g_l1 + (size_t)r0 * N + col) = make_float2(v0, v1);
                    if (r0 + 8 < M)
                        *(float2*)(g_l1 + (size_t)(r0 + 8) * N + col) = make_float2(v2, v3);
                }
            }
        }
    } else {
        // ---- fused classifier: partial logits for this block's 64 cols ----
        float plog[4][NC];              // rows: [mt0:r0, mt0:r0+8, mt1:r0, mt1:r0+8]
        #pragma unroll
        for (int r = 0; r < 4; r++)
            #pragma unroll
            for (int c = 0; c < NC; c++) plog[r][c] = 0.f;

        #pragma unroll
        for (int mt = 0; mt < 2; mt++) {
            #pragma unroll
            for (int nt = 0; nt < 4; nt++) {
                const int col = bn + wn + nt * 8 + qc * 2;
                if (col < N) {
                    float2 bv = *(const float2*)(bias + col);
                    float v0 = fmaxf(acc[mt][nt][0] + bv.x, 0.f);
                    float v1 = fmaxf(acc[mt][nt][1] + bv.y, 0.f);
                    float v2 = fmaxf(acc[mt][nt][2] + bv.x, 0.f);
                    float v3 = fmaxf(acc[mt][nt][3] + bv.y, 0.f);
                    const float* w0 = &sWc[(col - bn) * NC];
                    const float* w1 = w0 + NC;
                    #pragma unroll
                    for (int c = 0; c < NC; c++) {
                        plog[mt * 2 + 0][c] += v0 * w0[c] + v1 * w1[c];
                        plog[mt * 2 + 1][c] += v2 * w0[c] + v3 * w1[c];
                    }
                }
            }
        }
        // reduce across qc quad (lanes xor 1,2 share the same rows)
        #pragma unroll
        for (int off = 1; off <= 2; off <<= 1)
            #pragma unroll
            for (int r = 0; r < 4; r++)
                #pragma unroll
                for (int c = 0; c < NC; c++)
                    plog[r][c] += __shfl_xor_sync(0xFFFFFFFFu, plog[r][c], off);

        if (qc == 0) {
            #pragma unroll
            for (int mt = 0; mt < 2; mt++) {
                const int r0 = bm + wm + mt * 16 + qr;
                if (r0 < M)
                    #pragma unroll
                    for (int c = 0; c < NC; c++)
                        atomicAdd(&g_logits[(size_t)r0 * NC + c], plog[mt * 2][c]);
                if (r0 + 8 < M)
                    #pragma unroll
                    for (int c = 0; c < NC; c++)
                        atomicAdd(&g_logits[(size_t)(r0 + 8) * NC + c], plog[mt * 2 + 1][c]);
            }
        }
    }
}

// ---------------- logits init (bc) + final log_softmax ----------------
__global__ void k_logits_init(const float* __restrict__ bc) {
    int i = blockIdx.x * blockDim.x + threadIdx.x;
    if (i < NN * NC) g_logits[i] = bc[i % NC];
}

__global__ void k_logsoftmax(float* __restrict__ out) {
    int n = blockIdx.x * blockDim.x + threadIdx.x;
    if (n >= NN) return;
    float l[NC];
    float m = -1e30f;
    #pragma unroll
    for (int c = 0; c < NC; c++) {
        l[c] = g_logits[(size_t)n * NC + c];
        m = fmaxf(m, l[c]);
    }
    float s = 0.f;
    #pragma unroll
    for (int c = 0; c < NC; c++) s += expf(l[c] - m);
    float ls = m + logf(s);
    #pragma unroll
    for (int c = 0; c < NC; c++)
        out[(size_t)n * NC + c] = l[c] - ls;
}

// ---------------- launch ----------------
extern "C" void kernel_launch(void* const* d_in, const int* in_sizes, int n_in,
                              void* d_out, int out_size) {
    const float* x   = (const float*)d_in[0];
    const void*  ei  = d_in[1];                 // int32 or int64, detected on device
    const float* W1  = (const float*)d_in[2];
    const float* b1  = (const float*)d_in[3];
    const float* W2  = (const float*)d_in[4];
    const float* b2  = (const float*)d_in[5];
    const float* Wc  = (const float*)d_in[6];
    const float* bc  = (const float*)d_in[7];
    float*       out = (float*)d_out;

    const int T = 256;

    // dtype detect + clean index arrays
    k_detect<<<1, 32>>>((const unsigned int*)ei);
    k_convert_idx<<<(NE + T - 1) / T, T>>>(ei);

    // degrees + norms
    k_deg_init<<<(NN + T - 1) / T, T>>>();
    k_deg_acc <<<(NE + T - 1) / T, T>>>();
    k_dinv    <<<(NN + T - 1) / T, T>>>();
    k_norm    <<<(NE + T - 1) / T, T>>>();

    // aggx = S x
    {
        int total4 = NN * (F0 / 4);
        k_agg_init<1><<<(total4 + T - 1) / T, T>>>(x, F0 / 4, total4);
        long long tot = (long long)NE * (F0 / 4);
        k_scatter<1><<<(unsigned)((tot + T - 1) / T), T>>>(x, F0 / 4, tot);
    }

    // l1 = relu(aggx @ W1 + b1)
    gemm_mma<1><<<dim3((NN + 127) / 128, (F1 + 63) / 64), T>>>(W1, b1, nullptr, NN, F1, F0);

    // aggh = S l1
    {
        int total4 = NN * (F1 / 4);
        k_agg_init<2><<<(total4 + T - 1) / T, T>>>(nullptr, F1 / 4, total4);
        long long tot = (long long)NE * (F1 / 4);
        k_scatter<2><<<(unsigned)((tot + T - 1) / T), T>>>(nullptr, F1 / 4, tot);
    }

    // logits = bc;  then GEMM2 accumulates relu(aggh@W2+b2)@Wc atomically
    k_logits_init<<<(NN * NC + T - 1) / T, T>>>(bc);
    gemm_mma<2><<<dim3((NN + 127) / 128, (F2 + 63) / 64), T>>>(W2, b2, Wc, NN, F2, F1);

    // final log_softmax
    k_logsoftmax<<<(NN + T - 1) / T, T>>>(out);
}

// round 13
// speedup vs baseline: 3.2802x; 1.2767x over previous
#include <cuda_runtime.h>

// Problem constants (fixed by the dataset)
static constexpr int NN  = 50000;   // nodes
static constexpr int NE  = 400000;  // edges
static constexpr int F0  = 128;     // input features
static constexpr int F1  = 256;     // hidden 1
static constexpr int F2  = 784;     // hidden 2
static constexpr int NC  = 10;      // classes

// ---------------- device scratch (static, allocation-free) ----------------
// Referenced ONLY from device code (host-side use => cudaErrorInvalidAddressSpace).
//   g_aggx   = S x
//   g_l1     = relu(g_aggx @ W1 + b1)
//   g_aggh   = S g_l1
//   g_logits = bc + sum_tiles relu(g_aggh @ W2 + b2) @ Wc   (atomic accumulate)
//   out      = log_softmax(g_logits)
__device__ int   g_e64;
__device__ int   g_src32[NE];
__device__ int   g_dst32[NE];
__device__ float g_dinv[NN];
__device__ float g_norm[NE];
__device__ float g_aggx[(size_t)NN * F0];
__device__ float g_l1  [(size_t)NN * F1];
__device__ float g_aggh[(size_t)NN * F1];
__device__ float g_logits[(size_t)NN * NC];

// ---------------- dtype detection + index materialization ----------------
__global__ void k_detect(const unsigned int* __restrict__ ei32) {
    if (threadIdx.x == 0 && blockIdx.x == 0) {
        int all0 = 1;
        #pragma unroll 1
        for (int i = 0; i < 64; i++)
            if (ei32[2 * i + 1] != 0u) { all0 = 0; break; }
        g_e64 = all0;
    }
}

__device__ __forceinline__ int edge_idx(const void* ei, int half, int e) {
    if (g_e64) return (int)((const long long*)ei)[(size_t)half * NE + e];
    return ((const int*)ei)[(size_t)half * NE + e];
}

__global__ void k_convert_idx(const void* __restrict__ ei) {
    int e = blockIdx.x * blockDim.x + threadIdx.x;
    if (e < NE) {
        g_src32[e] = edge_idx(ei, 0, e);
        g_dst32[e] = edge_idx(ei, 1, e);
    }
}

// ---------------- degree / norm kernels ----------------
__global__ void k_deg_init() {
    int i = blockIdx.x * blockDim.x + threadIdx.x;
    if (i < NN) g_dinv[i] = 1.0f;
}

__global__ void k_deg_acc() {
    int e = blockIdx.x * blockDim.x + threadIdx.x;
    if (e < NE) atomicAdd(&g_dinv[g_dst32[e]], 1.0f);
}

__global__ void k_dinv() {
    int i = blockIdx.x * blockDim.x + threadIdx.x;
    if (i < NN) g_dinv[i] = rsqrtf(g_dinv[i]);
}

__global__ void k_norm() {
    int e = blockIdx.x * blockDim.x + threadIdx.x;
    if (e < NE) g_norm[e] = g_dinv[g_src32[e]] * g_dinv[g_dst32[e]];
}

// ---------------- aggregation init: agg = h * self_norm ----------------
template <int LAYER>
__global__ void k_agg_init(const float* __restrict__ hparam, int F4, int total4) {
    const float* __restrict__ h = (LAYER == 1) ? hparam : g_l1;
    float* __restrict__ agg = (LAYER == 1) ? g_aggx : g_aggh;

    int idx = blockIdx.x * blockDim.x + threadIdx.x;
    if (idx >= total4) return;
    int node = idx / F4;
    float sn = g_dinv[node];
    sn *= sn;                       // self_norm = 1/deg
    float4 v = *(const float4*)(h + (size_t)idx * 4);
    v.x *= sn; v.y *= sn; v.z *= sn; v.w *= sn;
    *(float4*)(agg + (size_t)idx * 4) = v;
}

// ---------------- edge scatter: agg[dst] += h[src] * norm (vector red) ----------------
template <int LAYER>
__global__ void k_scatter(const float* __restrict__ hparam, int F4, long long total) {
    const float* __restrict__ h = (LAYER == 1) ? hparam : g_l1;
    float* __restrict__ agg = (LAYER == 1) ? g_aggx : g_aggh;

    long long idx = (long long)blockIdx.x * blockDim.x + threadIdx.x;
    if (idx >= total) return;
    int e = (int)(idx / F4);
    int q = (int)(idx - (long long)e * F4);
    int s = g_src32[e];
    int d = g_dst32[e];
    float w = g_norm[e];
    float4 v = *(const float4*)(h + (size_t)s * (F4 * 4) + q * 4);
    float* o = agg + (size_t)d * (F4 * 4) + q * 4;
    asm volatile("red.global.add.v4.f32 [%0], {%1,%2,%3,%4};"
                 :: "l"(o), "f"(v.x * w), "f"(v.y * w), "f"(v.z * w), "f"(v.w * w)
                 : "memory");
}

// ---------------- bf16 split helpers ----------------
// pack (k_even, k_odd) floats as bf16x2 word: lower 16 = k_even.
__device__ __forceinline__ unsigned bf16pack(float e0, float e1) {
    unsigned r;
    asm("cvt.rn.bf16x2.f32 %0, %1, %2;" : "=r"(r) : "f"(e1), "f"(e0));
    return r;
}

// split two floats into bf16 hi-pack + bf16 residual-pack
__device__ __forceinline__ void bf16split(float e0, float e1, unsigned& h, unsigned& l) {
    h = bf16pack(e0, e1);
    float f0 = __uint_as_float(h << 16);
    float f1 = __uint_as_float(h & 0xFFFF0000u);
    l = bf16pack(e0 - f0, e1 - f1);
}

__device__ __forceinline__ void mma_bf16(float* d, const unsigned* a, const unsigned* b) {
    asm volatile(
        "mma.sync.aligned.m16n8k16.row.col.f32.bf16.bf16.f32 "
        "{%0,%1,%2,%3}, {%4,%5,%6,%7}, {%8,%9}, {%0,%1,%2,%3};"
        : "+f"(d[0]), "+f"(d[1]), "+f"(d[2]), "+f"(d[3])
        : "r"(a[0]), "r"(a[1]), "r"(a[2]), "r"(a[3]), "r"(b[0]), "r"(b[1]));
}

// ---------------- tensor-core GEMM (3xBF16 split, m16n8k16) ----------------
// LAYER==1: g_l1 = relu(g_aggx @ W1 + b1); store to gmem.     M=NN, N=F1, K=F0
// LAYER==2: relu(g_aggh @ W2 + b2) @ Wc -> atomic g_logits.   M=NN, N=F2, K=F1
// BM=128, BN=64, BK=16; 256 threads = 8 warps (4M x 2N); warp tile 32x32.
// Smem holds bf16x2 k-pairs, hi/lo pre-split; reg-prefetch of next stage.
template <int LAYER>
__global__ __launch_bounds__(256) void gemm_mma(const float* __restrict__ B,
                                                const float* __restrict__ bias,
                                                const float* __restrict__ Wc,
                                                int M, int N, int K) {
    const float* __restrict__ A = (LAYER == 1) ? g_aggx : g_aggh;

    constexpr int BM = 128, BN = 64, BK = 16;
    constexpr int ASTR = 12;   // pair stride: 12qr mod 32 distinct per quad-row -> conflict-free
    constexpr int BSTR = 72;   // 72 mod 32 == 8 -> qc*8+qr covers all banks

    __shared__ __align__(16) unsigned As_h[BM][ASTR];
    __shared__ __align__(16) unsigned As_l[BM][ASTR];
    __shared__ __align__(16) unsigned Bs_h[BK / 2][BSTR];
    __shared__ __align__(16) unsigned Bs_l[BK / 2][BSTR];
    __shared__ float sWc[(LAYER == 2) ? BN * NC : 1];

    const int tid  = threadIdx.x;
    const int bm   = blockIdx.x * BM;
    const int bn   = blockIdx.y * BN;
    const int warp = tid >> 5;
    const int lane = tid & 31;
    const int wm   = (warp & 3) * 32;
    const int wn   = (warp >> 2) * 32;
    const int qr   = lane >> 2;         // 0..7
    const int qc   = lane & 3;          // 0..3

    // staging maps
    const int ar  = tid >> 1;           // A row 0..127
    const int apc = (tid & 1) * 4;      // A pair-col base {0,4}
    const int bpr = tid >> 5;           // B pair-row 0..7
    const int bc0 = (tid & 31) * 2;     // B col base 0..62
    const bool bcv = (bn + bc0) < N;    // N even, bc0 even -> pairwise valid

    if (LAYER == 2) {
        for (int i = tid; i < BN * NC; i += 256) {
            int row = bn + i / NC;
            sWc[i] = (row < F2) ? Wc[(size_t)row * NC + (i % NC)] : 0.f;
        }
    }

    float acc[2][4][4] = {};

    // ---- prefetch stage 0 into registers ----
    float4 pa0 = make_float4(0.f, 0.f, 0.f, 0.f);
    float4 pa1 = make_float4(0.f, 0.f, 0.f, 0.f);
    float2 pb0 = make_float2(0.f, 0.f);
    float2 pb1 = make_float2(0.f, 0.f);
    if (bm + ar < M) {
        const float* ap = A + (size_t)(bm + ar) * K + apc * 2;
        pa0 = *(const float4*)ap;
        pa1 = *(const float4*)(ap + 4);
    }
    if (bcv) {
        pb0 = *(const float2*)(B + (size_t)(2 * bpr    ) * N + bn + bc0);
        pb1 = *(const float2*)(B + (size_t)(2 * bpr + 1) * N + bn + bc0);
    }

    for (int k0 = 0; k0 < K; k0 += BK) {
        // ---- convert + store prefetched stage ----
        {
            unsigned h0, l0, h1, l1, h2, l2, h3, l3;
            bf16split(pa0.x, pa0.y, h0, l0);
            bf16split(pa0.z, pa0.w, h1, l1);
            bf16split(pa1.x, pa1.y, h2, l2);
            bf16split(pa1.z, pa1.w, h3, l3);
            *(uint4*)&As_h[ar][apc] = make_uint4(h0, h1, h2, h3);
            *(uint4*)&As_l[ar][apc] = make_uint4(l0, l1, l2, l3);

            unsigned bh0, bl0, bh1, bl1;
            bf16split(pb0.x, pb1.x, bh0, bl0);   // col bc0:   (k even, k odd)
            bf16split(pb0.y, pb1.y, bh1, bl1);   // col bc0+1
            Bs_h[bpr][bc0]     = bh0;
            Bs_h[bpr][bc0 + 1] = bh1;
            Bs_l[bpr][bc0]     = bl0;
            Bs_l[bpr][bc0 + 1] = bl1;
        }
        __syncthreads();

        // ---- prefetch next stage (latency hidden under MMAs below) ----
        const int kn = k0 + BK;
        if (kn < K) {
            if (bm + ar < M) {
                const float* ap = A + (size_t)(bm + ar) * K + kn + apc * 2;
                pa0 = *(const float4*)ap;
                pa1 = *(const float4*)(ap + 4);
            }
            if (bcv) {
                pb0 = *(const float2*)(B + (size_t)(kn + 2 * bpr    ) * N + bn + bc0);
                pb1 = *(const float2*)(B + (size_t)(kn + 2 * bpr + 1) * N + bn + bc0);
            }
        }

        // ---- fragments + MMA (one k16 chunk per stage) ----
        unsigned ah[2][4], al[2][4];
        #pragma unroll
        for (int mt = 0; mt < 2; mt++) {
            const int rb = wm + mt * 16;
            ah[mt][0] = As_h[rb + qr    ][qc    ];
            ah[mt][1] = As_h[rb + qr + 8][qc    ];
            ah[mt][2] = As_h[rb + qr    ][qc + 4];
            ah[mt][3] = As_h[rb + qr + 8][qc + 4];
            al[mt][0] = As_l[rb + qr    ][qc    ];
            al[mt][1] = As_l[rb + qr + 8][qc    ];
            al[mt][2] = As_l[rb + qr    ][qc + 4];
            al[mt][3] = As_l[rb + qr + 8][qc + 4];
        }
        unsigned bh[4][2], bl[4][2];
        #pragma unroll
        for (int nt = 0; nt < 4; nt++) {
            const int col = wn + nt * 8 + qr;
            bh[nt][0] = Bs_h[qc    ][col];
            bh[nt][1] = Bs_h[qc + 4][col];
            bl[nt][0] = Bs_l[qc    ][col];
            bl[nt][1] = Bs_l[qc + 4][col];
        }
        #pragma unroll
        for (int mt = 0; mt < 2; mt++)
            #pragma unroll
            for (int nt = 0; nt < 4; nt++) {
                mma_bf16(acc[mt][nt], ah[mt], bh[nt]);
                mma_bf16(acc[mt][nt], ah[mt], bl[nt]);
                mma_bf16(acc[mt][nt], al[mt], bh[nt]);
            }
        __syncthreads();
    }

    if (LAYER == 1) {
        #pragma unroll
        for (int mt = 0; mt < 2; mt++) {
            const int r0 = bm + wm + mt * 16 + qr;
            #pragma unroll
            for (int nt = 0; nt < 4; nt++) {
                const int col = bn + wn + nt * 8 + qc * 2;
                if (col < N) {
                    float2 bv = *(const float2*)(bias + col);
                    float v0 = fmaxf(acc[mt][nt][0] + bv.x, 0.f);
                    float v1 = fmaxf(acc[mt][nt][1] + bv.y, 0.f);
                    float v2 = fmaxf(acc[mt][nt][2] + bv.x, 0.f);
                    float v3 = fmaxf(acc[mt][nt][3] + bv.y, 0.f);
                    if (r0 < M)
                        *(float2*)(g_l1 + (size_t)r0 * N + col) = make_float2(v0, v1);
                    if (r0 + 8 < M)
                        *(float2*)(g_l1 + (size_t)(r0 + 8) * N + col) = make_float2(v2, v3);
                }
            }
        }
    } else {
        // ---- fused classifier: partial logits for this block's 64 cols ----
        float plog[4][NC];
        #pragma unroll
        for (int r = 0; r < 4; r++)
            #pragma unroll
            for (int c = 0; c < NC; c++) plog[r][c] = 0.f;

        #pragma unroll
        for (int mt = 0; mt < 2; mt++) {
            #pragma unroll
            for (int nt = 0; nt < 4; nt++) {
                const int col = bn + wn + nt * 8 + qc * 2;
                if (col < N) {
                    float2 bv = *(const float2*)(bias + col);
                    float v0 = fmaxf(acc[mt][nt][0] + bv.x, 0.f);
                    float v1 = fmaxf(acc[mt][nt][1] + bv.y, 0.f);
                    float v2 = fmaxf(acc[mt][nt][2] + bv.x, 0.f);
                    float v3 = fmaxf(acc[mt][nt][3] + bv.y, 0.f);
                    const float* w0 = &sWc[(col - bn) * NC];
                    const float* w1 = w0 + NC;
                    #pragma unroll
                    for (int c = 0; c < NC; c++) {
                        plog[mt * 2 + 0][c] += v0 * w0[c] + v1 * w1[c];
                        plog[mt * 2 + 1][c] += v2 * w0[c] + v3 * w1[c];
                    }
                }
            }
        }
        #pragma unroll
        for (int off = 1; off <= 2; off <<= 1)
            #pragma unroll
            for (int r = 0; r < 4; r++)
                #pragma unroll
                for (int c = 0; c < NC; c++)
                    plog[r][c] += __shfl_xor_sync(0xFFFFFFFFu, plog[r][c], off);

        if (qc == 0) {
            #pragma unroll
            for (int mt = 0; mt < 2; mt++) {
                const int r0 = bm + wm + mt * 16 + qr;
                if (r0 < M)
                    #pragma unroll
                    for (int c = 0; c < NC; c++)
                        atomicAdd(&g_logits[(size_t)r0 * NC + c], plog[mt * 2][c]);
                if (r0 + 8 < M)
                    #pragma unroll
                    for (int c = 0; c < NC; c++)
                        atomicAdd(&g_logits[(size_t)(r0 + 8) * NC + c], plog[mt * 2 + 1][c]);
            }
        }
    }
}

// ---------------- logits init (bc) + final log_softmax ----------------
__global__ void k_logits_init(const float* __restrict__ bc) {
    int i = blockIdx.x * blockDim.x + threadIdx.x;
    if (i < NN * NC) g_logits[i] = bc[i % NC];
}

__global__ void k_logsoftmax(float* __restrict__ out) {
    int n = blockIdx.x * blockDim.x + threadIdx.x;
    if (n >= NN) return;
    float l[NC];
    float m = -1e30f;
    #pragma unroll
    for (int c = 0; c < NC; c++) {
        l[c] = g_logits[(size_t)n * NC + c];
        m = fmaxf(m, l[c]);
    }
    float s = 0.f;
    #pragma unroll
    for (int c = 0; c < NC; c++) s += expf(l[c] - m);
    float ls = m + logf(s);
    #pragma unroll
    for (int c = 0; c < NC; c++)
        out[(size_t)n * NC + c] = l[c] - ls;
}

// ---------------- launch ----------------
extern "C" void kernel_launch(void* const* d_in, const int* in_sizes, int n_in,
                              void* d_out, int out_size) {
    const float* x   = (const float*)d_in[0];
    const void*  ei  = d_in[1];
    const float* W1  = (const float*)d_in[2];
    const float* b1  = (const float*)d_in[3];
    const float* W2  = (const float*)d_in[4];
    const float* b2  = (const float*)d_in[5];
    const float* Wc  = (const float*)d_in[6];
    const float* bc  = (const float*)d_in[7];
    float*       out = (float*)d_out;

    const int T = 256;

    k_detect<<<1, 32>>>((const unsigned int*)ei);
    k_convert_idx<<<(NE + T - 1) / T, T>>>(ei);

    k_deg_init<<<(NN + T - 1) / T, T>>>();
    k_deg_acc <<<(NE + T - 1) / T, T>>>();
    k_dinv    <<<(NN + T - 1) / T, T>>>();
    k_norm    <<<(NE + T - 1) / T, T>>>();

    // aggx = S x
    {
        int total4 = NN * (F0 / 4);
        k_agg_init<1><<<(total4 + T - 1) / T, T>>>(x, F0 / 4, total4);
        long long tot = (long long)NE * (F0 / 4);
        k_scatter<1><<<(unsigned)((tot + T - 1) / T), T>>>(x, F0 / 4, tot);
    }

    // l1 = relu(aggx @ W1 + b1)
    gemm_mma<1><<<dim3((NN + 127) / 128, (F1 + 63) / 64), T>>>(W1, b1, nullptr, NN, F1, F0);

    // aggh = S l1
    {
        int total4 = NN * (F1 / 4);
        k_agg_init<2><<<(total4 + T - 1) / T, T>>>(nullptr, F1 / 4, total4);
        long long tot = (long long)NE * (F1 / 4);
        k_scatter<2><<<(unsigned)((tot + T - 1) / T), T>>>(nullptr, F1 / 4, tot);
    }

    // logits = bc; GEMM2 accumulates relu(aggh@W2+b2)@Wc atomically
    k_logits_init<<<(NN * NC + T - 1) / T, T>>>(bc);
    gemm_mma<2><<<dim3((NN + 127) / 128, (F2 + 63) / 64), T>>>(W2, b2, Wc, NN, F2, F1);

    k_logsoftmax<<<(NN + T - 1) / T, T>>>(out);
}